// round 4
// baseline (speedup 1.0000x reference)
#include <cuda_runtime.h>
#include <cuda_fp16.h>
#include <cstdint>

#define NB 32
#define NS 8
#define NT 512
#define NC 128
#define NH 128

// Scratch (allocation-free rule: module-scope device arrays)
static __device__ __align__(16) __half g_q[(size_t)NB * NT * NH];
static __device__ __align__(16) __half g_k[(size_t)NB * NT * NH];
static __device__ __align__(16) __half g_v[(size_t)NB * NT * NH];
static __device__ __align__(16) float  g_s[(size_t)NB * NT * NT];

__device__ __forceinline__ uint32_t smem_u32(const void* p) {
    return (uint32_t)__cvta_generic_to_shared(p);
}

__device__ __forceinline__ void ldm_x4(uint32_t& r0, uint32_t& r1, uint32_t& r2, uint32_t& r3, uint32_t addr) {
    asm volatile("ldmatrix.sync.aligned.m8n8.x4.shared.b16 {%0,%1,%2,%3}, [%4];"
                 : "=r"(r0), "=r"(r1), "=r"(r2), "=r"(r3) : "r"(addr));
}
__device__ __forceinline__ void ldm_x2(uint32_t& r0, uint32_t& r1, uint32_t addr) {
    asm volatile("ldmatrix.sync.aligned.m8n8.x2.shared.b16 {%0,%1}, [%2];"
                 : "=r"(r0), "=r"(r1) : "r"(addr));
}
__device__ __forceinline__ void ldm_x2_trans(uint32_t& r0, uint32_t& r1, uint32_t addr) {
    asm volatile("ldmatrix.sync.aligned.m8n8.x2.trans.shared.b16 {%0,%1}, [%2];"
                 : "=r"(r0), "=r"(r1) : "r"(addr));
}
__device__ __forceinline__ void mma_16816(float& d0, float& d1, float& d2, float& d3,
                                          uint32_t a0, uint32_t a1, uint32_t a2, uint32_t a3,
                                          uint32_t b0, uint32_t b1) {
    asm volatile("mma.sync.aligned.m16n8k16.row.col.f32.f16.f16.f32 "
                 "{%0,%1,%2,%3}, {%4,%5,%6,%7}, {%8,%9}, {%0,%1,%2,%3};"
                 : "+f"(d0), "+f"(d1), "+f"(d2), "+f"(d3)
                 : "r"(a0), "r"(a1), "r"(a2), "r"(a3), "r"(b0), "r"(b1));
}
__device__ __forceinline__ void cp16(uint32_t smem_addr, const void* gptr) {
    asm volatile("cp.async.cg.shared.global [%0], [%1], 16;" :: "r"(smem_addr), "l"(gptr));
}
__device__ __forceinline__ void cp_commit() { asm volatile("cp.async.commit_group;"); }
__device__ __forceinline__ void cp_wait0()  { asm volatile("cp.async.wait_group 0;"); }

// ---------------------------------------------------------------------------
// Kernel 1: QKV projections.  grid = (NB*NT/64, 3), block = 256.
// ---------------------------------------------------------------------------
__global__ void __launch_bounds__(256) qkv_kernel(const float* __restrict__ x,
                                                  const float* __restrict__ Wq,
                                                  const float* __restrict__ Wk,
                                                  const float* __restrict__ Wv) {
    __shared__ __half sx[64][136];
    __shared__ __half sw[64][136];

    const int tid = threadIdx.x, lane = tid & 31, w = tid >> 5;
    const float* W = (blockIdx.y == 0) ? Wq : (blockIdx.y == 1) ? Wk : Wv;
    __half* outp   = (blockIdx.y == 0) ? g_q : (blockIdx.y == 1) ? g_k : g_v;
    const int row0 = blockIdx.x * 64;

    #pragma unroll
    for (int i = 0; i < 8; i++) {
        int f = tid + i * 256;
        int r = f >> 5, c4 = f & 31;
        float4 v4 = *(const float4*)(x + (size_t)(row0 + r) * NC + c4 * 4);
        __half2* dst = (__half2*)&sx[r][c4 * 4];
        dst[0] = __floats2half2_rn(v4.x, v4.y);
        dst[1] = __floats2half2_rn(v4.z, v4.w);
    }

    float acc[8][4];
    #pragma unroll
    for (int j = 0; j < 8; j++)
        #pragma unroll
        for (int q = 0; q < 4; q++) acc[j][q] = 0.f;

    const int tblk = (w >> 1) * 16, hsb = (w & 1) * 64;

    for (int kh = 0; kh < 2; kh++) {
        __syncthreads();
        #pragma unroll
        for (int i = 0; i < 8; i++) {
            int f = tid + i * 256;
            int r = f >> 5, c4 = f & 31;
            float4 v4 = *(const float4*)(W + (size_t)(kh * 64 + r) * NH + c4 * 4);
            __half2* dst = (__half2*)&sw[r][c4 * 4];
            dst[0] = __floats2half2_rn(v4.x, v4.y);
            dst[1] = __floats2half2_rn(v4.z, v4.w);
        }
        __syncthreads();
        #pragma unroll
        for (int kk = 0; kk < 4; kk++) {
            uint32_t a0, a1, a2, a3;
            ldm_x4(a0, a1, a2, a3,
                   smem_u32(&sx[tblk + (lane & 15)][(kh * 4 + kk) * 16 + ((lane >> 4) << 3)]));
            #pragma unroll
            for (int j = 0; j < 8; j++) {
                uint32_t b0, b1;
                ldm_x2_trans(b0, b1, smem_u32(&sw[kk * 16 + (lane & 15)][hsb + j * 8]));
                mma_16816(acc[j][0], acc[j][1], acc[j][2], acc[j][3], a0, a1, a2, a3, b0, b1);
            }
        }
    }

    const int g = lane >> 2, c2 = (lane & 3) * 2;
    #pragma unroll
    for (int j = 0; j < 8; j++) {
        *(__half2*)&outp[(size_t)(row0 + tblk + g) * NH + hsb + j * 8 + c2] =
            __floats2half2_rn(acc[j][0], acc[j][1]);
        *(__half2*)&outp[(size_t)(row0 + tblk + 8 + g) * NH + hsb + j * 8 + c2] =
            __floats2half2_rn(acc[j][2], acc[j][3]);
    }
}

// ---------------------------------------------------------------------------
// Kernel 2: scores[b,t,u] = (q[b,t] . k[b,u]) * C^-0.5  (fp32)
// ---------------------------------------------------------------------------
__global__ void __launch_bounds__(256) scores_kernel() {
    __shared__ __half sq_[64][136];
    __shared__ __half sk_[64][136];
    const int tid = threadIdx.x, lane = tid & 31, w = tid >> 5;
    const int t0 = blockIdx.x * 64, u0 = blockIdx.y * 64, b = blockIdx.z;

    const __half* qb = g_q + (size_t)b * NT * NH;
    const __half* kb = g_k + (size_t)b * NT * NH;
    #pragma unroll
    for (int i = 0; i < 4; i++) {
        int f = tid + i * 256;
        int r = f >> 4, c8 = (f & 15) * 8;
        *(uint4*)&sq_[r][c8] = *(const uint4*)(qb + (size_t)(t0 + r) * NH + c8);
        *(uint4*)&sk_[r][c8] = *(const uint4*)(kb + (size_t)(u0 + r) * NH + c8);
    }
    __syncthreads();

    const int tblk = (w >> 1) * 16, ub = (w & 1) * 32;
    float acc[4][4];
    #pragma unroll
    for (int j = 0; j < 4; j++)
        #pragma unroll
        for (int q = 0; q < 4; q++) acc[j][q] = 0.f;

    #pragma unroll
    for (int kk = 0; kk < 8; kk++) {
        uint32_t a0, a1, a2, a3;
        ldm_x4(a0, a1, a2, a3,
               smem_u32(&sq_[tblk + (lane & 15)][kk * 16 + ((lane >> 4) << 3)]));
        #pragma unroll
        for (int j = 0; j < 4; j++) {
            uint32_t b0, b1;
            ldm_x2(b0, b1, smem_u32(&sk_[ub + j * 8 + (lane & 7)][kk * 16 + ((lane >> 3) & 1) * 8]));
            mma_16816(acc[j][0], acc[j][1], acc[j][2], acc[j][3], a0, a1, a2, a3, b0, b1);
        }
    }

    const float sc = 0.08838834764831845f;  // 128^-0.5
    const int g = lane >> 2, c2 = (lane & 3) * 2;
    float* srow = g_s + (size_t)b * NT * NT;
    #pragma unroll
    for (int j = 0; j < 4; j++) {
        *(float2*)&srow[(size_t)(t0 + tblk + g) * NT + u0 + ub + j * 8 + c2] =
            make_float2(acc[j][0] * sc, acc[j][1] * sc);
        *(float2*)&srow[(size_t)(t0 + tblk + 8 + g) * NT + u0 + ub + j * 8 + c2] =
            make_float2(acc[j][2] * sc, acc[j][3] * sc);
    }
}

// ---------------------------------------------------------------------------
// Kernel 3: attention, software-pipelined.  grid = (NT/64, NS, NB), block=256.
// Per iteration it (u-chunk of 64):
//   compute p = exp(adj*score) from regs PREFETCHED in it-1; write sp; row-sums
//   prefetch adj/score regs for it+1 (overlaps wait+BAR+MMA+BAR of it)
//   cp.async.wait (v tile it ready) ; BAR1 ; MMA(sp, sv) ; BAR2 ;
//   cp.async v tile it+1 (safe: all MMA(it) reads of sv done; overlaps exp of it+1)
// ---------------------------------------------------------------------------
__global__ void __launch_bounds__(256) attn_kernel(const float* __restrict__ adj,
                                                   float* __restrict__ outp) {
    __shared__ __half sp[64][72];     // p tile fp16 (single buffer; guarded by BAR1/BAR2)
    __shared__ __half sv[64][136];    // v tile fp16 (single buffer; cp.async after BAR2)
    __shared__ float  sl[64];         // row sums

    const int tid = threadIdx.x, lane = tid & 31, w = tid >> 5;
    const int t0 = blockIdx.x * 64, s = blockIdx.y, b = blockIdx.z;

    const float*  adj_base = adj + ((size_t)(b * NS + s) * NT + t0) * NT;
    const float*  sc_base  = g_s + ((size_t)b * NT + t0) * NT;
    const __half* vb       = g_v + (size_t)b * NT * NH;

    if (tid < 64) sl[tid] = 0.f;

    const int r = tid >> 2, cqb = (tid & 3) * 16;     // softmax-phase mapping
    const int tblk = (w >> 1) * 16, hsb = (w & 1) * 64;

    const float* arow = adj_base + (size_t)r * NT + cqb;
    const float* srow = sc_base + (size_t)r * NT + cqb;

    // v-tile cp.async: 4 x 16B per thread
    const int vr = tid >> 4, vc = (tid & 15) * 8;     // 4 rows apart per i

    float acc[8][4];
    #pragma unroll
    for (int j = 0; j < 8; j++)
        #pragma unroll
        for (int q = 0; q < 4; q++) acc[j][q] = 0.f;

    // ---- prologue: v tile 0 via cp.async; adj/score regs for it=0 ----
    #pragma unroll
    for (int i = 0; i < 4; i++)
        cp16(smem_u32(&sv[vr + i * 16][vc]), vb + (size_t)(vr + i * 16) * NH + vc);
    cp_commit();

    float4 pa[4], ps4[4];
    #pragma unroll
    for (int i = 0; i < 4; i++) {
        pa[i]  = *(const float4*)(arow + i * 4);
        ps4[i] = *(const float4*)(srow + i * 4);
    }
    __syncthreads();   // sl init visible before first accumulation

    for (int it = 0; it < 8; it++) {
        // ---- compute p from prefetched regs ----
        float psum = 0.f;
        __align__(16) __half2 ph[8];
        #pragma unroll
        for (int i = 0; i < 4; i++) {
            float p0 = __expf(pa[i].x * ps4[i].x);
            float p1 = __expf(pa[i].y * ps4[i].y);
            float p2 = __expf(pa[i].z * ps4[i].z);
            float p3 = __expf(pa[i].w * ps4[i].w);
            psum += (p0 + p1) + (p2 + p3);
            ph[i * 2]     = __floats2half2_rn(p0, p1);
            ph[i * 2 + 1] = __floats2half2_rn(p2, p3);
        }
        *(uint4*)&sp[r][cqb]     = *(uint4*)&ph[0];
        *(uint4*)&sp[r][cqb + 8] = *(uint4*)&ph[4];

        psum += __shfl_xor_sync(0xffffffffu, psum, 1);
        psum += __shfl_xor_sync(0xffffffffu, psum, 2);
        if ((tid & 3) == 0) sl[r] += psum;   // unique writer per row

        // ---- prefetch adj/score regs for it+1 (long latency hidden by MMA) ----
        if (it < 7) {
            const float* an = arow + (it + 1) * 64;
            const float* sn = srow + (it + 1) * 64;
            #pragma unroll
            for (int i = 0; i < 4; i++) {
                pa[i]  = *(const float4*)(an + i * 4);
                ps4[i] = *(const float4*)(sn + i * 4);
            }
        }

        cp_wait0();        // sv tile for this iteration resident
        __syncthreads();   // BAR1: sp + sv ready for all

        // ---- acc += p[64,64] @ v[64,128] ----
        #pragma unroll
        for (int kk = 0; kk < 4; kk++) {
            uint32_t a0, a1, a2, a3;
            ldm_x4(a0, a1, a2, a3,
                   smem_u32(&sp[tblk + (lane & 15)][kk * 16 + ((lane >> 4) << 3)]));
            #pragma unroll
            for (int j = 0; j < 8; j++) {
                uint32_t b0, b1;
                ldm_x2_trans(b0, b1, smem_u32(&sv[kk * 16 + (lane & 15)][hsb + j * 8]));
                mma_16816(acc[j][0], acc[j][1], acc[j][2], acc[j][3], a0, a1, a2, a3, b0, b1);
            }
        }
        __syncthreads();   // BAR2: all MMA reads of sp/sv complete

        // ---- v tile for it+1 (overlaps next exp phase) ----
        if (it < 7) {
            const __half* vn = vb + (size_t)(it + 1) * 64 * NH;
            #pragma unroll
            for (int i = 0; i < 4; i++)
                cp16(smem_u32(&sv[vr + i * 16][vc]), vn + (size_t)(vr + i * 16) * NH + vc);
            cp_commit();
        }
    }

    const int g = lane >> 2, c2 = (lane & 3) * 2;
    const float il0 = 1.f / sl[tblk + g];
    const float il1 = 1.f / sl[tblk + 8 + g];
    float* ob = outp + ((size_t)(b * NS + s) * NT + t0) * NH;
    #pragma unroll
    for (int j = 0; j < 8; j++) {
        *(float2*)&ob[(size_t)(tblk + g) * NH + hsb + j * 8 + c2] =
            make_float2(acc[j][0] * il0, acc[j][1] * il0);
        *(float2*)&ob[(size_t)(tblk + 8 + g) * NH + hsb + j * 8 + c2] =
            make_float2(acc[j][2] * il1, acc[j][3] * il1);
    }
}

// ---------------------------------------------------------------------------
extern "C" void kernel_launch(void* const* d_in, const int* in_sizes, int n_in,
                              void* d_out, int out_size) {
    (void)in_sizes; (void)n_in; (void)out_size;
    const float* x   = (const float*)d_in[0];
    const float* adj = (const float*)d_in[1];
    const float* Wq  = (const float*)d_in[2];
    const float* Wk  = (const float*)d_in[3];
    const float* Wv  = (const float*)d_in[4];
    float* out = (float*)d_out;

    qkv_kernel<<<dim3(NB * NT / 64, 3, 1), 256>>>(x, Wq, Wk, Wv);
    scores_kernel<<<dim3(NT / 64, NT / 64, NB), 256>>>();
    attn_kernel<<<dim3(NT / 64, NS, NB), 256>>>(adj, out);
}